// round 2
// baseline (speedup 1.0000x reference)
#include <cuda_runtime.h>

// GeneralizedGraphDiffusion: out = prelu((sum_k theta_k*T_k * a) @ x) @ W^T + b
// N=8192, D=128, K=4.
// R2: TPB 224->448 (14 warps/SM), double-buffered smem staging with ONE
// __syncthreads per tile, f32x2 packed FMA. BM=56 -> 147 blocks = 1 wave.

#define NN 8192
#define DD 128
#define BM 56
#define BJ 32
#define TPB 448
#define NTILES (NN / BJ)
#define BUFF 6144   // floats per buffer: qs 32*64 + xs 32*128

__device__ __forceinline__ unsigned long long pack2(float lo, float hi) {
    unsigned long long r;
    asm("mov.b64 %0, {%1, %2};" : "=l"(r) : "f"(lo), "f"(hi));
    return r;
}
__device__ __forceinline__ void unpack2(unsigned long long v, float &lo, float &hi) {
    asm("mov.b64 {%0, %1}, %2;" : "=f"(lo), "=f"(hi) : "l"(v));
}
__device__ __forceinline__ unsigned long long fma2(unsigned long long a,
                                                   unsigned long long b,
                                                   unsigned long long c) {
    unsigned long long d;
    asm("fma.rn.f32x2 %0, %1, %2, %3;" : "=l"(d) : "l"(a), "l"(b), "l"(c));
    return d;
}

struct Pref {
    float4 pT[4];   // one 4-wide quad from each of the K=4 slices
    float4 pa;      // matching quad of a
    float4 px[3];   // x staging (448*2 + 128 float4 = 1024 total)
};

__device__ __forceinline__ void prefetch(Pref &P,
                                         const float *__restrict__ T,
                                         const float *__restrict__ a,
                                         const float *__restrict__ x,
                                         size_t rb, size_t slice,
                                         int j0, int tid) {
    const float *xsrc = x + (size_t)j0 * DD;
    P.px[0] = *(const float4 *)(xsrc + tid * 4);
    P.px[1] = *(const float4 *)(xsrc + (tid + TPB) * 4);
    if (tid < 128)
        P.px[2] = *(const float4 *)(xsrc + (tid + 2 * TPB) * 4);
    const size_t o = rb + (size_t)j0;
#pragma unroll
    for (int k = 0; k < 4; k++)
        P.pT[k] = *(const float4 *)(T + k * slice + o);
    P.pa = *(const float4 *)(a + o);
}

__device__ __forceinline__ void stage(const Pref &P, float *qs, float *xs,
                                      float th0, float th1, float th2, float th3,
                                      int row, int jq, int tid) {
    float4 t0 = P.pT[0], t1 = P.pT[1], t2 = P.pT[2], t3 = P.pT[3];
    float4 av = P.pa;
    float qx = (th0 * t0.x + th1 * t1.x + th2 * t2.x + th3 * t3.x) * av.x;
    float qy = (th0 * t0.y + th1 * t1.y + th2 * t2.y + th3 * t3.y) * av.y;
    float qz = (th0 * t0.z + th1 * t1.z + th2 * t2.z + th3 * t3.z) * av.z;
    float qw = (th0 * t0.w + th1 * t1.w + th2 * t2.w + th3 * t3.w) * av.w;
    int base = (jq * 4) * 64 + row;   // qs[jj][row], stride 64 (rows 0..55 used)
    qs[base]       = qx;
    qs[base + 64]  = qy;
    qs[base + 128] = qz;
    qs[base + 192] = qw;

    *(float4 *)(xs + tid * 4) = P.px[0];
    *(float4 *)(xs + (tid + TPB) * 4) = P.px[1];
    if (tid < 128)
        *(float4 *)(xs + (tid + 2 * TPB) * 4) = P.px[2];
}

__global__ __launch_bounds__(TPB, 1)
void ggd_kernel(const float *__restrict__ theta,
                const float *__restrict__ T,
                const float *__restrict__ x,
                const float *__restrict__ a,
                const float *__restrict__ alpha,
                const float *__restrict__ W,
                const float *__restrict__ bias,
                float *__restrict__ out) {
    __shared__ __align__(16) float smem[2 * BUFF];   // 48 KB
    float *hs = smem;   // [BM][128] = 7168 floats, overlaid after mainloop

    const int tid = threadIdx.x;
    const int tx = tid & 15;     // col group (8 cols)
    const int ty = tid >> 4;     // row group (2 rows), 0..27
    const int ty2 = ty * 2;
    const int tx8 = tx * 8;
    const int i0 = blockIdx.x * BM;

    const float th0 = __ldg(theta + 0);
    const float th1 = __ldg(theta + 1);
    const float th2 = __ldg(theta + 2);
    const float th3 = __ldg(theta + 3);

    // q-construction: 448 quads = 56 rows x 8 j-quads, exactly 1 per thread
    const int row = tid >> 3, jq = tid & 7;
    int gi = i0 + row; if (gi > NN - 1) gi = NN - 1;
    const size_t slice = (size_t)NN * NN;
    const size_t rb = (size_t)gi * NN + jq * 4;

    // accumulators: 2 rows x 8 cols as 2x4 f32x2 pairs
    unsigned long long acc[2][4];
#pragma unroll
    for (int m = 0; m < 2; m++)
#pragma unroll
        for (int p = 0; p < 4; p++) acc[m][p] = 0ULL;

    Pref P;
    prefetch(P, T, a, x, rb, slice, 0, tid);

    for (int t = 0; t < NTILES; t++) {
        float *qs = smem + (t & 1) * BUFF;
        float *xs = qs + 2048;

        stage(P, qs, xs, th0, th1, th2, th3, row, jq, tid);
        __syncthreads();
        if (t + 1 < NTILES)
            prefetch(P, T, a, x, rb, slice, (t + 1) * BJ, tid);

#pragma unroll 8
        for (int jj = 0; jj < BJ; jj++) {
            float2 qv = *(const float2 *)(qs + jj * 64 + ty2);
            unsigned long long q0 = pack2(qv.x, qv.x);
            unsigned long long q1 = pack2(qv.y, qv.y);
            const ulonglong2 xa = *(const ulonglong2 *)(xs + jj * DD + tx8);
            const ulonglong2 xb = *(const ulonglong2 *)(xs + jj * DD + tx8 + 4);
            acc[0][0] = fma2(xa.x, q0, acc[0][0]);
            acc[0][1] = fma2(xa.y, q0, acc[0][1]);
            acc[0][2] = fma2(xb.x, q0, acc[0][2]);
            acc[0][3] = fma2(xb.y, q0, acc[0][3]);
            acc[1][0] = fma2(xa.x, q1, acc[1][0]);
            acc[1][1] = fma2(xa.y, q1, acc[1][1]);
            acc[1][2] = fma2(xb.x, q1, acc[1][2]);
            acc[1][3] = fma2(xb.y, q1, acc[1][3]);
        }
    }

    // ---- epilogue: PReLU -> hs (smem), then out = hs @ W^T + b ----
    __syncthreads();   // all compute reads of staging buffers done

    float4 al0 = *(const float4 *)(alpha + tx8);
    float4 al1 = *(const float4 *)(alpha + tx8 + 4);
    float alf[8] = {al0.x, al0.y, al0.z, al0.w, al1.x, al1.y, al1.z, al1.w};

#pragma unroll
    for (int m = 0; m < 2; m++) {
        float v[8];
#pragma unroll
        for (int p = 0; p < 4; p++) unpack2(acc[m][p], v[2 * p], v[2 * p + 1]);
#pragma unroll
        for (int u = 0; u < 8; u++) v[u] = v[u] > 0.f ? v[u] : alf[u] * v[u];
        int r = ty2 + m;
        *(float4 *)(hs + r * DD + tx8) = make_float4(v[0], v[1], v[2], v[3]);
        *(float4 *)(hs + r * DD + tx8 + 4) = make_float4(v[4], v[5], v[6], v[7]);
    }
    __syncthreads();

    float oa[2][8];
#pragma unroll
    for (int m = 0; m < 2; m++)
#pragma unroll
        for (int u = 0; u < 8; u++) oa[m][u] = 0.f;

    for (int c4 = 0; c4 < DD / 4; c4++) {
        float4 wv[8];
#pragma unroll
        for (int u = 0; u < 8; u++)
            wv[u] = *(const float4 *)(W + (size_t)(tx8 + u) * DD + c4 * 4);
#pragma unroll
        for (int m = 0; m < 2; m++) {
            float4 hv = *(const float4 *)(hs + (ty2 + m) * DD + c4 * 4);
#pragma unroll
            for (int u = 0; u < 8; u++)
                oa[m][u] += hv.x * wv[u].x + hv.y * wv[u].y +
                            hv.z * wv[u].z + hv.w * wv[u].w;
        }
    }

    float4 b0 = *(const float4 *)(bias + tx8);
    float4 b1 = *(const float4 *)(bias + tx8 + 4);
#pragma unroll
    for (int m = 0; m < 2; m++) {
        int go = i0 + ty2 + m;
        if (go < NN) {
            float4 o0 = make_float4(oa[m][0] + b0.x, oa[m][1] + b0.y,
                                    oa[m][2] + b0.z, oa[m][3] + b0.w);
            float4 o1 = make_float4(oa[m][4] + b1.x, oa[m][5] + b1.y,
                                    oa[m][6] + b1.z, oa[m][7] + b1.w);
            *(float4 *)(out + (size_t)go * DD + tx8) = o0;
            *(float4 *)(out + (size_t)go * DD + tx8 + 4) = o1;
        }
    }
}

extern "C" void kernel_launch(void *const *d_in, const int *in_sizes, int n_in,
                              void *d_out, int out_size) {
    const float *theta = (const float *)d_in[0];
    const float *T     = (const float *)d_in[1];
    const float *x     = (const float *)d_in[2];
    const float *a     = (const float *)d_in[3];
    const float *alpha = (const float *)d_in[4];
    const float *W     = (const float *)d_in[5];
    const float *bias  = (const float *)d_in[6];
    float *out = (float *)d_out;
    (void)in_sizes; (void)n_in; (void)out_size;

    ggd_kernel<<<(NN + BM - 1) / BM, TPB>>>(theta, T, x, a, alpha, W, bias, out);
}

// round 3
// speedup vs baseline: 1.6463x; 1.6463x over previous
#include <cuda_runtime.h>

// GeneralizedGraphDiffusion: out = prelu((sum_k theta_k*T_k * a) @ x) @ W^T + b
// N=8192, D=128, K=4.
// R2: TPB 224->448 (14 warps/SM), double-buffered smem staging with ONE
// __syncthreads per tile, f32x2 packed FMA. BM=56 -> 147 blocks = 1 wave.

#define NN 8192
#define DD 128
#define BM 56
#define BJ 32
#define TPB 448
#define NTILES (NN / BJ)
#define BUFF 6144   // floats per buffer: qs 32*64 + xs 32*128

__device__ __forceinline__ unsigned long long pack2(float lo, float hi) {
    unsigned long long r;
    asm("mov.b64 %0, {%1, %2};" : "=l"(r) : "f"(lo), "f"(hi));
    return r;
}
__device__ __forceinline__ void unpack2(unsigned long long v, float &lo, float &hi) {
    asm("mov.b64 {%0, %1}, %2;" : "=f"(lo), "=f"(hi) : "l"(v));
}
__device__ __forceinline__ unsigned long long fma2(unsigned long long a,
                                                   unsigned long long b,
                                                   unsigned long long c) {
    unsigned long long d;
    asm("fma.rn.f32x2 %0, %1, %2, %3;" : "=l"(d) : "l"(a), "l"(b), "l"(c));
    return d;
}

struct Pref {
    float4 pT[4];   // one 4-wide quad from each of the K=4 slices
    float4 pa;      // matching quad of a
    float4 px[3];   // x staging (448*2 + 128 float4 = 1024 total)
};

__device__ __forceinline__ void prefetch(Pref &P,
                                         const float *__restrict__ T,
                                         const float *__restrict__ a,
                                         const float *__restrict__ x,
                                         size_t rb, size_t slice,
                                         int j0, int tid) {
    const float *xsrc = x + (size_t)j0 * DD;
    P.px[0] = *(const float4 *)(xsrc + tid * 4);
    P.px[1] = *(const float4 *)(xsrc + (tid + TPB) * 4);
    if (tid < 128)
        P.px[2] = *(const float4 *)(xsrc + (tid + 2 * TPB) * 4);
    const size_t o = rb + (size_t)j0;
#pragma unroll
    for (int k = 0; k < 4; k++)
        P.pT[k] = *(const float4 *)(T + k * slice + o);
    P.pa = *(const float4 *)(a + o);
}

__device__ __forceinline__ void stage(const Pref &P, float *qs, float *xs,
                                      float th0, float th1, float th2, float th3,
                                      int row, int jq, int tid) {
    float4 t0 = P.pT[0], t1 = P.pT[1], t2 = P.pT[2], t3 = P.pT[3];
    float4 av = P.pa;
    float qx = (th0 * t0.x + th1 * t1.x + th2 * t2.x + th3 * t3.x) * av.x;
    float qy = (th0 * t0.y + th1 * t1.y + th2 * t2.y + th3 * t3.y) * av.y;
    float qz = (th0 * t0.z + th1 * t1.z + th2 * t2.z + th3 * t3.z) * av.z;
    float qw = (th0 * t0.w + th1 * t1.w + th2 * t2.w + th3 * t3.w) * av.w;
    int base = (jq * 4) * 64 + row;   // qs[jj][row], stride 64 (rows 0..55 used)
    qs[base]       = qx;
    qs[base + 64]  = qy;
    qs[base + 128] = qz;
    qs[base + 192] = qw;

    *(float4 *)(xs + tid * 4) = P.px[0];
    *(float4 *)(xs + (tid + TPB) * 4) = P.px[1];
    if (tid < 128)
        *(float4 *)(xs + (tid + 2 * TPB) * 4) = P.px[2];
}

__global__ __launch_bounds__(TPB, 1)
void ggd_kernel(const float *__restrict__ theta,
                const float *__restrict__ T,
                const float *__restrict__ x,
                const float *__restrict__ a,
                const float *__restrict__ alpha,
                const float *__restrict__ W,
                const float *__restrict__ bias,
                float *__restrict__ out) {
    __shared__ __align__(16) float smem[2 * BUFF];   // 48 KB
    float *hs = smem;   // [BM][128] = 7168 floats, overlaid after mainloop

    const int tid = threadIdx.x;
    const int tx = tid & 15;     // col group (8 cols)
    const int ty = tid >> 4;     // row group (2 rows), 0..27
    const int ty2 = ty * 2;
    const int tx8 = tx * 8;
    const int i0 = blockIdx.x * BM;

    const float th0 = __ldg(theta + 0);
    const float th1 = __ldg(theta + 1);
    const float th2 = __ldg(theta + 2);
    const float th3 = __ldg(theta + 3);

    // q-construction: 448 quads = 56 rows x 8 j-quads, exactly 1 per thread
    const int row = tid >> 3, jq = tid & 7;
    int gi = i0 + row; if (gi > NN - 1) gi = NN - 1;
    const size_t slice = (size_t)NN * NN;
    const size_t rb = (size_t)gi * NN + jq * 4;

    // accumulators: 2 rows x 8 cols as 2x4 f32x2 pairs
    unsigned long long acc[2][4];
#pragma unroll
    for (int m = 0; m < 2; m++)
#pragma unroll
        for (int p = 0; p < 4; p++) acc[m][p] = 0ULL;

    Pref P;
    prefetch(P, T, a, x, rb, slice, 0, tid);

    for (int t = 0; t < NTILES; t++) {
        float *qs = smem + (t & 1) * BUFF;
        float *xs = qs + 2048;

        stage(P, qs, xs, th0, th1, th2, th3, row, jq, tid);
        __syncthreads();
        if (t + 1 < NTILES)
            prefetch(P, T, a, x, rb, slice, (t + 1) * BJ, tid);

#pragma unroll 8
        for (int jj = 0; jj < BJ; jj++) {
            float2 qv = *(const float2 *)(qs + jj * 64 + ty2);
            unsigned long long q0 = pack2(qv.x, qv.x);
            unsigned long long q1 = pack2(qv.y, qv.y);
            const ulonglong2 xa = *(const ulonglong2 *)(xs + jj * DD + tx8);
            const ulonglong2 xb = *(const ulonglong2 *)(xs + jj * DD + tx8 + 4);
            acc[0][0] = fma2(xa.x, q0, acc[0][0]);
            acc[0][1] = fma2(xa.y, q0, acc[0][1]);
            acc[0][2] = fma2(xb.x, q0, acc[0][2]);
            acc[0][3] = fma2(xb.y, q0, acc[0][3]);
            acc[1][0] = fma2(xa.x, q1, acc[1][0]);
            acc[1][1] = fma2(xa.y, q1, acc[1][1]);
            acc[1][2] = fma2(xb.x, q1, acc[1][2]);
            acc[1][3] = fma2(xb.y, q1, acc[1][3]);
        }
    }

    // ---- epilogue: PReLU -> hs (smem), then out = hs @ W^T + b ----
    __syncthreads();   // all compute reads of staging buffers done

    float4 al0 = *(const float4 *)(alpha + tx8);
    float4 al1 = *(const float4 *)(alpha + tx8 + 4);
    float alf[8] = {al0.x, al0.y, al0.z, al0.w, al1.x, al1.y, al1.z, al1.w};

#pragma unroll
    for (int m = 0; m < 2; m++) {
        float v[8];
#pragma unroll
        for (int p = 0; p < 4; p++) unpack2(acc[m][p], v[2 * p], v[2 * p + 1]);
#pragma unroll
        for (int u = 0; u < 8; u++) v[u] = v[u] > 0.f ? v[u] : alf[u] * v[u];
        int r = ty2 + m;
        *(float4 *)(hs + r * DD + tx8) = make_float4(v[0], v[1], v[2], v[3]);
        *(float4 *)(hs + r * DD + tx8 + 4) = make_float4(v[4], v[5], v[6], v[7]);
    }
    __syncthreads();

    float oa[2][8];
#pragma unroll
    for (int m = 0; m < 2; m++)
#pragma unroll
        for (int u = 0; u < 8; u++) oa[m][u] = 0.f;

    for (int c4 = 0; c4 < DD / 4; c4++) {
        float4 wv[8];
#pragma unroll
        for (int u = 0; u < 8; u++)
            wv[u] = *(const float4 *)(W + (size_t)(tx8 + u) * DD + c4 * 4);
#pragma unroll
        for (int m = 0; m < 2; m++) {
            float4 hv = *(const float4 *)(hs + (ty2 + m) * DD + c4 * 4);
#pragma unroll
            for (int u = 0; u < 8; u++)
                oa[m][u] += hv.x * wv[u].x + hv.y * wv[u].y +
                            hv.z * wv[u].z + hv.w * wv[u].w;
        }
    }

    float4 b0 = *(const float4 *)(bias + tx8);
    float4 b1 = *(const float4 *)(bias + tx8 + 4);
#pragma unroll
    for (int m = 0; m < 2; m++) {
        int go = i0 + ty2 + m;
        if (go < NN) {
            float4 o0 = make_float4(oa[m][0] + b0.x, oa[m][1] + b0.y,
                                    oa[m][2] + b0.z, oa[m][3] + b0.w);
            float4 o1 = make_float4(oa[m][4] + b1.x, oa[m][5] + b1.y,
                                    oa[m][6] + b1.z, oa[m][7] + b1.w);
            *(float4 *)(out + (size_t)go * DD + tx8) = o0;
            *(float4 *)(out + (size_t)go * DD + tx8 + 4) = o1;
        }
    }
}

extern "C" void kernel_launch(void *const *d_in, const int *in_sizes, int n_in,
                              void *d_out, int out_size) {
    const float *theta = (const float *)d_in[0];
    const float *T     = (const float *)d_in[1];
    const float *x     = (const float *)d_in[2];
    const float *a     = (const float *)d_in[3];
    const float *alpha = (const float *)d_in[4];
    const float *W     = (const float *)d_in[5];
    const float *bias  = (const float *)d_in[6];
    float *out = (float *)d_out;
    (void)in_sizes; (void)n_in; (void)out_size;

    ggd_kernel<<<(NN + BM - 1) / BM, TPB>>>(theta, T, x, a, alpha, W, bias, out);
}

// round 6
// speedup vs baseline: 4.8534x; 2.9481x over previous
#include <cuda_runtime.h>
#include <cstdint>

// GeneralizedGraphDiffusion: out = prelu((sum_k theta_k*T_k * a) @ x) @ W^T + b
// N=8192, D=128, K=4.
// R6: warp-level mma.sync tf32 (HMMA on sm_103 — tcgen05 rejected by this
// toolchain's sm_103 PTX target). 128 CTAs x 64 rows, full K per CTA,
// q built in registers, double-buffered smem, 1 syncthreads/tile.

#define NN 8192
#define DDIM 128
#define BK 32
#define NT (NN / BK)         // 256 tiles
#define TPB 256

// smem word offsets (floats)
#define AB0 0
#define BB0 2304             // A = 64*36
#define AB1 6400             // BB0 + 4096
#define BB1 8704
#define SMEM_WORDS 12800     // 51200 bytes
#define HS_STRIDE 132

__device__ __forceinline__ uint32_t tf32r(float f) {
    uint32_t r;
    asm("cvt.rna.tf32.f32 %0, %1;" : "=r"(r) : "f"(f));
    return r;
}
__device__ __forceinline__ void mma8(float* c, uint32_t a0, uint32_t a1,
                                     uint32_t a2, uint32_t a3,
                                     uint32_t b0, uint32_t b1) {
    asm volatile(
        "mma.sync.aligned.m16n8k8.row.col.f32.tf32.tf32.f32 "
        "{%0,%1,%2,%3}, {%4,%5,%6,%7}, {%8,%9}, {%0,%1,%2,%3};"
        : "+f"(c[0]), "+f"(c[1]), "+f"(c[2]), "+f"(c[3])
        : "r"(a0), "r"(a1), "r"(a2), "r"(a3), "r"(b0), "r"(b1));
}

extern __shared__ float sm[];

__global__ __launch_bounds__(TPB, 1)
void ggd_kernel(const float* __restrict__ theta, const float* __restrict__ T,
                const float* __restrict__ x, const float* __restrict__ a,
                const float* __restrict__ alpha, const float* __restrict__ W,
                const float* __restrict__ bias, float* __restrict__ out) {
    const int tid = threadIdx.x;
    const int wid = tid >> 5, lane = tid & 31;
    const int g = lane >> 2, tig = lane & 3;       // groupID, threadID_in_group
    const int wr = wid & 1, wc = wid >> 1;         // warp tile: 32 rows x 32 cols
    const int i0 = blockIdx.x * 64;

    const float th0 = __ldg(theta), th1 = __ldg(theta + 1),
                th2 = __ldg(theta + 2), th3 = __ldg(theta + 3);
    const size_t slice = (size_t)NN * NN;

    // ---- A staging assignment: 512 quads (row 0..63, c4 0..7), 2/thread ----
    const int rowA0 = tid >> 3,            cA0 = (tid & 7) * 4;
    const int rowA1 = (tid + 256) >> 3,    cA1 = ((tid + 256) & 7) * 4;
    const size_t rbA0 = (size_t)(i0 + rowA0) * NN + cA0;
    const size_t rbA1 = (size_t)(i0 + rowA1) * NN + cA1;
    const int stA0 = rowA0 * 36 + cA0;     // word offset within A buffer
    const int stA1 = rowA1 * 36 + cA1;

    // ---- B staging assignment: n = tid&127, khalf = tid>>7 ----
    const int bn = tid & 127, kh = tid >> 7;
    const int bnf = bn >> 3, bg = bn & 7;

    float4 pT[2][4], pa[2];
    float px[16];

#define LOADR(J0) do {                                                         \
    size_t _o0 = rbA0 + (size_t)(J0);                                          \
    size_t _o1 = rbA1 + (size_t)(J0);                                          \
    pT[0][0] = *(const float4*)(T + _o0);           pT[1][0] = *(const float4*)(T + _o1); \
    pT[0][1] = *(const float4*)(T + slice + _o0);   pT[1][1] = *(const float4*)(T + slice + _o1); \
    pT[0][2] = *(const float4*)(T + 2*slice + _o0); pT[1][2] = *(const float4*)(T + 2*slice + _o1); \
    pT[0][3] = *(const float4*)(T + 3*slice + _o0); pT[1][3] = *(const float4*)(T + 3*slice + _o1); \
    pa[0] = *(const float4*)(a + _o0);              pa[1] = *(const float4*)(a + _o1); \
    const float* _xp = x + (size_t)((J0) + kh * 16) * DDIM + bn;               \
    _Pragma("unroll") for (int _j = 0; _j < 16; _j++) px[_j] = __ldg(_xp + _j * DDIM); \
} while (0)

#define STOREB(Abase, Bbase) do {                                              \
    _Pragma("unroll") for (int _s = 0; _s < 2; _s++) {                         \
        float4 t0 = pT[_s][0], t1 = pT[_s][1], t2 = pT[_s][2], t3 = pT[_s][3], av = pa[_s]; \
        uint32_t qx = tf32r((th0*t0.x + th1*t1.x + th2*t2.x + th3*t3.x) * av.x); \
        uint32_t qy = tf32r((th0*t0.y + th1*t1.y + th2*t2.y + th3*t3.y) * av.y); \
        uint32_t qz = tf32r((th0*t0.z + th1*t1.z + th2*t2.z + th3*t3.z) * av.z); \
        uint32_t qw = tf32r((th0*t0.w + th1*t1.w + th2*t2.w + th3*t3.w) * av.w); \
        uint32_t* _d = (uint32_t*)(sm + (Abase) + (_s ? stA1 : stA0));         \
        asm volatile("st.shared.v4.b32 [%0], {%1,%2,%3,%4};" ::                \
            "l"(_d), "r"(qx), "r"(qy), "r"(qz), "r"(qw) : "memory");           \
    }                                                                          \
    _Pragma("unroll") for (int _ksl = 0; _ksl < 2; _ksl++) {                   \
        int _ks = kh * 2 + _ksl;                                               \
        uint32_t v0 = tf32r(px[_ksl*8 + 0]), v1 = tf32r(px[_ksl*8 + 4]);       \
        uint32_t v2 = tf32r(px[_ksl*8 + 1]), v3 = tf32r(px[_ksl*8 + 5]);       \
        uint32_t v4 = tf32r(px[_ksl*8 + 2]), v5 = tf32r(px[_ksl*8 + 6]);       \
        uint32_t v6 = tf32r(px[_ksl*8 + 3]), v7 = tf32r(px[_ksl*8 + 7]);       \
        uint32_t* _d = (uint32_t*)(sm + (Bbase) + bnf*256 + _ks*64 + bg*8);    \
        asm volatile("st.shared.v4.b32 [%0], {%1,%2,%3,%4};" ::                \
            "l"(_d), "r"(v0), "r"(v1), "r"(v2), "r"(v3) : "memory");           \
        asm volatile("st.shared.v4.b32 [%0], {%1,%2,%3,%4};" ::                \
            "l"(_d + 4), "r"(v4), "r"(v5), "r"(v6), "r"(v7) : "memory");       \
    }                                                                          \
} while (0)

    float acc[2][4][4];
#pragma unroll
    for (int mi = 0; mi < 2; mi++)
#pragma unroll
        for (int nf = 0; nf < 4; nf++)
#pragma unroll
            for (int e = 0; e < 4; e++) acc[mi][nf][e] = 0.f;

    LOADR(0);
    for (int t = 0; t < NT; t++) {
        const int Abase = (t & 1) ? AB1 : AB0;
        const int Bbase = (t & 1) ? BB1 : BB0;
        STOREB(Abase, Bbase);
        __syncthreads();
        if (t + 1 < NT) LOADR((t + 1) * BK);

        const uint32_t* As = (const uint32_t*)(sm + Abase);
        const uint32_t* Bs = (const uint32_t*)(sm + Bbase);
#pragma unroll
        for (int ks = 0; ks < 4; ks++) {
            uint32_t af[2][4];
#pragma unroll
            for (int mi = 0; mi < 2; mi++) {
                const uint32_t* ap = As + (wr*32 + mi*16 + g) * 36 + ks*8 + tig;
                af[mi][0] = ap[0];
                af[mi][1] = ap[8 * 36];
                af[mi][2] = ap[4];
                af[mi][3] = ap[8 * 36 + 4];
            }
#pragma unroll
            for (int nfl = 0; nfl < 4; nfl++) {
                const int nf = wc * 4 + nfl;
                uint2 bb = *(const uint2*)(Bs + ((nf*4 + ks)*32 + lane)*2);
#pragma unroll
                for (int mi = 0; mi < 2; mi++)
                    mma8(acc[mi][nfl], af[mi][0], af[mi][1], af[mi][2], af[mi][3],
                         bb.x, bb.y);
            }
        }
    }

    // ---- epilogue: acc -> hs (raw h), then prelu + projection ----
    __syncthreads();
    float* hs = sm;   // [64][HS_STRIDE]
#pragma unroll
    for (int mi = 0; mi < 2; mi++)
#pragma unroll
        for (int nfl = 0; nfl < 4; nfl++) {
            const int col = (wc*4 + nfl)*8 + tig*2;
            const int r0 = wr*32 + mi*16 + g;
            *(float2*)(hs + r0 * HS_STRIDE + col) =
                make_float2(acc[mi][nfl][0], acc[mi][nfl][1]);
            *(float2*)(hs + (r0 + 8) * HS_STRIDE + col) =
                make_float2(acc[mi][nfl][2], acc[mi][nfl][3]);
        }
    __syncthreads();

    const int tx = tid & 15, ty = tid >> 4;
    const int tx8 = tx * 8, ty4 = ty * 4;
    float oa[4][8];
#pragma unroll
    for (int m = 0; m < 4; m++)
#pragma unroll
        for (int u = 0; u < 8; u++) oa[m][u] = 0.f;

    for (int c4 = 0; c4 < 32; c4++) {
        float4 al = __ldg((const float4*)(alpha + c4 * 4));
        float4 wv[8];
#pragma unroll
        for (int u = 0; u < 8; u++)
            wv[u] = __ldg((const float4*)(W + (size_t)(tx8 + u) * DDIM + c4 * 4));
#pragma unroll
        for (int m = 0; m < 4; m++) {
            float4 hv = *(const float4*)(hs + (ty4 + m) * HS_STRIDE + c4 * 4);
            hv.x = hv.x > 0.f ? hv.x : al.x * hv.x;
            hv.y = hv.y > 0.f ? hv.y : al.y * hv.y;
            hv.z = hv.z > 0.f ? hv.z : al.z * hv.z;
            hv.w = hv.w > 0.f ? hv.w : al.w * hv.w;
#pragma unroll
            for (int u = 0; u < 8; u++)
                oa[m][u] += hv.x * wv[u].x + hv.y * wv[u].y +
                            hv.z * wv[u].z + hv.w * wv[u].w;
        }
    }

    float4 b0 = __ldg((const float4*)(bias + tx8));
    float4 b1 = __ldg((const float4*)(bias + tx8 + 4));
#pragma unroll
    for (int m = 0; m < 4; m++) {
        size_t go = (size_t)(i0 + ty4 + m) * DDIM;
        *(float4*)(out + go + tx8) = make_float4(oa[m][0] + b0.x, oa[m][1] + b0.y,
                                                 oa[m][2] + b0.z, oa[m][3] + b0.w);
        *(float4*)(out + go + tx8 + 4) = make_float4(oa[m][4] + b1.x, oa[m][5] + b1.y,
                                                     oa[m][6] + b1.z, oa[m][7] + b1.w);
    }
}

extern "C" void kernel_launch(void* const* d_in, const int* in_sizes, int n_in,
                              void* d_out, int out_size) {
    const float* theta = (const float*)d_in[0];
    const float* T     = (const float*)d_in[1];
    const float* x     = (const float*)d_in[2];
    const float* a     = (const float*)d_in[3];
    const float* alpha = (const float*)d_in[4];
    const float* W     = (const float*)d_in[5];
    const float* bias  = (const float*)d_in[6];
    (void)in_sizes; (void)n_in; (void)out_size;

    cudaFuncSetAttribute(ggd_kernel, cudaFuncAttributeMaxDynamicSharedMemorySize,
                         SMEM_WORDS * 4);
    ggd_kernel<<<NN / 64, TPB, SMEM_WORDS * 4>>>(theta, T, x, a, alpha, W, bias,
                                                 (float*)d_out);
}